// round 17
// baseline (speedup 1.0000x reference)
#include <cuda_runtime.h>
#include <cuda_bf16.h>
#include <math.h>

// ---------------------------------------------------------------------------
// AttentionalLaneLSTM: M=4096, N=256, EMB=64, H=128, ENC=128, T=100.
// Tensor-core recurrence: G = bias + [h|e][rows x192] @ [Whh;Wih]
// mma.sync.m16n8k16 bf16, 3-term hi/lo split (~fp32 accuracy).
// R16: CTA split into two independent 256-thread halves (32 rows each) with
// named barriers -> half A's epilogue/barrier overlaps half B's HMMA burst.
// ---------------------------------------------------------------------------
#define M_MAX   4096
#define T_STEPS 100
#define EMBD    64
#define HID     128
#define NOBS    256
#define MR      64            // rows per CTA (32 per half)
#define KT      12            // 192/16 k-tiles (k<128 -> Whh, k>=128 -> Wih)
#define XS      200           // X smem row stride (bf16 elems)
#define SRS     132           // sred row stride (float2 elems)

typedef unsigned int uint;
typedef unsigned long long ull;

// Scratch (device globals — no dynamic allocation allowed)
__device__ float g_scores[NOBS * T_STEPS];
// fragment-ready B: [dir][ntile 64][ktile 12][lane 32] -> uint2
//  n = nt*8 + lane/4 ; k0 = kt*16 + 2*(lane&3); .x={k0,k0+1} .y={k0+8,k0+9}
__device__ uint2 g_Bhi[2 * 64 * KT * 32];
__device__ uint2 g_Blo[2 * 64 * KT * 32];
// embeddings e[t][row][64] bf16 hi/lo (dir-independent)
__device__ __nv_bfloat16 g_ehi[(long)T_STEPS * M_MAX * EMBD];
__device__ __nv_bfloat16 g_elo[(long)T_STEPS * M_MAX * EMBD];
__device__ float g_pre[M_MAX * 1024];

__device__ __forceinline__ ull pack2(float a, float b) {
    ull r; asm("mov.b64 %0, {%1,%2};" : "=l"(r) : "f"(a), "f"(b)); return r;
}
__device__ __forceinline__ float2 unpack2(ull v) {
    float2 r; asm("mov.b64 {%0,%1}, %2;" : "=f"(r.x), "=f"(r.y) : "l"(v)); return r;
}
__device__ __forceinline__ void fma2(ull& acc, ull a, ull b) {
    asm("fma.rn.f32x2 %0, %1, %2, %0;" : "+l"(acc) : "l"(a), "l"(b));
}
__device__ __forceinline__ uint s2u(const void* p) {
    return (uint)__cvta_generic_to_shared(p);
}
__device__ __forceinline__ uint pkbf(float lo, float hi) {
    __nv_bfloat162 v = __floats2bfloat162_rn(lo, hi);
    return *(uint*)&v;
}
__device__ __forceinline__ float sigf(float x) {
    return __fdividef(1.0f, 1.0f + __expf(-x));
}
__device__ __forceinline__ float tanhfast(float x) {
    return __fdividef(2.0f, 1.0f + __expf(-2.0f * x)) - 1.0f;
}

#define LDM4(R, addr) \
    asm volatile("ldmatrix.sync.aligned.m8n8.x4.shared.b16 {%0,%1,%2,%3}, [%4];" \
                 : "=r"((R)[0]), "=r"((R)[1]), "=r"((R)[2]), "=r"((R)[3]) : "r"(addr))
#define MMAB(D, A, b) \
    asm volatile("mma.sync.aligned.m16n8k16.row.col.f32.bf16.bf16.f32 " \
                 "{%0,%1,%2,%3}, {%4,%5,%6,%7}, {%8,%9}, {%0,%1,%2,%3};" \
                 : "+f"((D)[0]), "+f"((D)[1]), "+f"((D)[2]), "+f"((D)[3]) \
                 : "r"((A)[0]), "r"((A)[1]), "r"((A)[2]), "r"((A)[3]), \
                   "r"((b).x), "r"((b).y))
#define GBAR(id) \
    asm volatile("bar.sync %0, %1;" :: "r"(id), "r"(256) : "memory")

// ---------------------------------------------------------------------------
// Kernel 1: build fragment-ready B tables (bf16 hi/lo split)
// ---------------------------------------------------------------------------
__global__ void pack_kernel(const float* __restrict__ Wih_f,
                            const float* __restrict__ Whh_f,
                            const float* __restrict__ Wih_b,
                            const float* __restrict__ Whh_b) {
    int idx = blockIdx.x * blockDim.x + threadIdx.x;
    if (idx >= 2 * 64 * KT * 32) return;
    int lane = idx & 31;
    int kt   = (idx >> 5) % KT;
    int nt   = (idx >> 5) / KT % 64;
    int d    = idx / (64 * KT * 32);
    int n  = nt * 8 + (lane >> 2);
    int k0 = kt * 16 + 2 * (lane & 3);
    const float* Whh = d ? Whh_b : Whh_f;
    const float* Wih = d ? Wih_b : Wih_f;
    float wv[4]; float hi[4], lo[4];
#pragma unroll
    for (int i = 0; i < 4; i++) {
        int k = k0 + (i >> 1) * 8 + (i & 1);
        wv[i] = (k < HID) ? Whh[k * 512 + n] : Wih[(k - HID) * 512 + n];
        hi[i] = __bfloat162float(__float2bfloat16(wv[i]));
        lo[i] = wv[i] - hi[i];
    }
    uint2 H, L;
    H.x = pkbf(hi[0], hi[1]); H.y = pkbf(hi[2], hi[3]);
    L.x = pkbf(lo[0], lo[1]); L.y = pkbf(lo[2], lo[3]);
    g_Bhi[idx] = H;
    g_Blo[idx] = L;
}

// ---------------------------------------------------------------------------
// Kernel 2: attention scores = softmax(relu(obs @ attn_W + attn_b), axis=1)
// ---------------------------------------------------------------------------
__global__ void attn_kernel(const float* __restrict__ obs,
                            const float* __restrict__ W,
                            const float* __restrict__ b) {
    int n = blockIdx.x, tid = threadIdx.x;
    __shared__ float obs_s[128];
    __shared__ float red[128];
    obs_s[tid] = obs[n * 128 + tid];
    __syncthreads();
    float a = -1e30f;
    if (tid < T_STEPS) {
        a = b[tid];
#pragma unroll 8
        for (int k = 0; k < 128; k++) a = fmaf(obs_s[k], W[k * T_STEPS + tid], a);
        a = fmaxf(a, 0.0f);
    }
    red[tid] = a;
    __syncthreads();
    for (int s = 64; s > 0; s >>= 1) {
        if (tid < s) red[tid] = fmaxf(red[tid], red[tid + s]);
        __syncthreads();
    }
    float m = red[0];
    __syncthreads();
    float e = 0.0f;
    if (tid < T_STEPS) e = expf(a - m);
    red[tid] = e;
    __syncthreads();
    for (int s = 64; s > 0; s >>= 1) {
        if (tid < s) red[tid] += red[tid + s];
        __syncthreads();
    }
    if (tid < T_STEPS) g_scores[n * T_STEPS + tid] = e / red[0];
}

// ---------------------------------------------------------------------------
// Kernel 3: embeddings e[t][row][64] = relu(feat4 @ embW + embB), bf16 hi/lo
// ---------------------------------------------------------------------------
__global__ void embed_kernel(const float* __restrict__ lf,
                             const float* __restrict__ embW,
                             const float* __restrict__ embB, int Mrows) {
    long idx = (long)blockIdx.x * blockDim.x + threadIdx.x;
    long total = (long)T_STEPS * Mrows * EMBD;
    if (idx >= total) return;
    int j   = (int)(idx & 63);
    long q  = idx >> 6;
    int row = (int)(q % Mrows);
    int t   = (int)(q / Mrows);
    const float* fb = lf + (long)row * 600 + 200 + t * 4;
    float v = embB[j];
    v = fmaf(fb[0], embW[j],        v);
    v = fmaf(fb[1], embW[64  + j],  v);
    v = fmaf(fb[2], embW[128 + j],  v);
    v = fmaf(fb[3], embW[192 + j],  v);
    v = fmaxf(v, 0.0f);
    float hi = __bfloat162float(__float2bfloat16(v));
    g_ehi[idx] = __float2bfloat16(v);
    g_elo[idx] = __float2bfloat16(v - hi);
}

// ---------------------------------------------------------------------------
// Kernel 4: tensor-core bidirectional LSTM, two independent 256-thread halves.
// Half grp owns rows [grp*32, grp*32+32) with its own X double-buffers and
// named barrier (id grp+1). Warp within half: wl = w&7, mt = wl&1 (16 rows),
// q = wl>>1 (32 units). Per step: mma reads X[cur], epilogue + e-stage write
// X[nxt], ONE named barrier, swap. Term-major mma (dep distance 4).
// ---------------------------------------------------------------------------
extern __shared__ char dynsmem[];

// per-half region: Xhi0,Xhi1,Xlo0,Xlo1 (4 x 12800) + sred (32*SRS*8 = 33792)
#define GSZ      84992
#define OFF_SB   (2 * GSZ)            // 169984
#define OFF_MROW (OFF_SB + 2048)      // 172032
#define LSTM_SMEM (OFF_MROW + 256)    // 172288

__global__ void __launch_bounds__(512, 1)
lstm_kernel(const float* __restrict__ h0, const float* __restrict__ c0,
            const float* __restrict__ b_f, const float* __restrict__ b_b,
            const int*   __restrict__ mask, int Mrows) {
    int nblk = Mrows / MR;                 // 64
    int dir  = blockIdx.x / nblk;
    int mblk = blockIdx.x % nblk;
    int r0   = mblk * MR;
    int tid  = threadIdx.x;
    int grp  = tid >> 8;                   // half id: 0 or 1
    int tidg = tid & 255;
    int w = tid >> 5, lane = tid & 31;
    int wl = w & 7;
    int mt = wl & 1, q = wl >> 1;
    int tq = lane & 3;

    char* gb = dynsmem + grp * GSZ;
    __nv_bfloat16* Xhi[2] = { (__nv_bfloat16*)(gb),
                              (__nv_bfloat16*)(gb + 12800) };
    __nv_bfloat16* Xlo[2] = { (__nv_bfloat16*)(gb + 25600),
                              (__nv_bfloat16*)(gb + 38400) };
    float2* sred = (float2*)(gb + 51200);          // (hmax, hatt) per (row,u)
    float*  sb   = (float*)(dynsmem + OFF_SB);
    int*    smrow= (int*)(dynsmem + OFF_MROW);

    const float* bias = dir ? b_b : b_f;
    sb[tid] = bias[tid];
    if (tid < MR) smrow[tid] = mask[r0 + tid];
    // init h columns of this half's X[0], init sred (rows 0..31 local)
    for (int i = tidg; i < 32 * HID; i += 256) {
        int row = i >> 7, u = i & 127;
        float h = h0[dir * HID + u];
        float hh = __bfloat162float(__float2bfloat16(h));
        Xhi[0][row * XS + u] = __float2bfloat16(h);
        Xlo[0][row * XS + u] = __float2bfloat16(h - hh);
        sred[row * SRS + u] = make_float2(-1e30f, 0.0f);
    }
    // stage e(t0) into this half's X[0]
    {
        int t0 = dir ? (T_STEPS - 1) : 0;
        const uint4* sh = (const uint4*)(g_ehi + ((long)t0 * Mrows + r0 + grp * 32) * EMBD);
        const uint4* sl = (const uint4*)(g_elo + ((long)t0 * Mrows + r0 + grp * 32) * EMBD);
        int row = tidg >> 3, c8 = tidg & 7;
        *(uint4*)&Xhi[0][row * XS + HID + c8 * 8] = sh[tidg];
        *(uint4*)&Xlo[0][row * XS + HID + c8 * 8] = sl[tidg];
    }
    __syncthreads();   // once: covers cross-half sb/smrow visibility

    // per-thread rows: local (X/sred) and CTA-global (mask/g_pre)
    int rloc = mt * 16 + (lane >> 2);      // 0..31 within half
    int rlocB = rloc + 8;
    int rA = grp * 32 + rloc;              // 0..63 within CTA
    int rB = rA + 8;

    float cst[4][4];
#pragma unroll
    for (int ut = 0; ut < 4; ut++) {
        int uA = q * 32 + ut * 8 + 2 * tq;
        float cA = c0[dir * HID + uA], cB = c0[dir * HID + uA + 1];
        cst[ut][0] = cA; cst[ut][1] = cB; cst[ut][2] = cA; cst[ut][3] = cB;
    }

    // ldmatrix sources (TL,BL,TR,BR of the 16x16 A tile), local rows
    int arow = mt * 16 + (lane & 7) + ((lane >> 3) & 1) * 8;
    int acolb = ((lane >> 4) & 1) * 8;
    uint aHi[2] = { s2u(Xhi[0] + arow * XS + acolb), s2u(Xhi[1] + arow * XS + acolb) };
    uint aLo[2] = { s2u(Xlo[0] + arow * XS + acolb), s2u(Xlo[1] + arow * XS + acolb) };

    const uint2* Bhi0 = g_Bhi + ((long)(dir * 64 + q * 4) * KT) * 32 + lane;
    const uint2* Blo0 = g_Blo + ((long)(dir * 64 + q * 4) * KT) * 32 + lane;

    int cur = 0;
    for (int s = 0; s < T_STEPS; s++) {
        int t = dir ? (T_STEPS - 1 - s) : s;
        int nxt = cur ^ 1;

        float acc[4][4][4];
#pragma unroll
        for (int ut = 0; ut < 4; ut++)
#pragma unroll
            for (int g = 0; g < 4; g++)
#pragma unroll
                for (int j = 0; j < 4; j++) acc[ut][g][j] = 0.0f;

        for (int kt = 0; kt < KT; kt++) {
            uint Ah[4], Al[4];
            LDM4(Ah, aHi[cur] + kt * 32);
            LDM4(Al, aLo[cur] + kt * 32);
#pragma unroll
            for (int g = 0; g < 4; g++) {
                uint2 bh[4], bl[4];
#pragma unroll
                for (int ut = 0; ut < 4; ut++) {
                    long off = ((long)(g * 16 + ut) * KT + kt) * 32;
                    bh[ut] = Bhi0[off];
                    bl[ut] = Blo0[off];
                }
                // term-major: same-acc dependency distance = 4 mmas
#pragma unroll
                for (int ut = 0; ut < 4; ut++) MMAB(acc[ut][g], Ah, bh[ut]);
#pragma unroll
                for (int ut = 0; ut < 4; ut++) MMAB(acc[ut][g], Ah, bl[ut]);
#pragma unroll
                for (int ut = 0; ut < 4; ut++) MMAB(acc[ut][g], Al, bh[ut]);
            }
        }

        // attention weights (2 per thread per step)
        float avA = __ldg(&g_scores[smrow[rA] * T_STEPS + t]);
        float avB = __ldg(&g_scores[smrow[rB] * T_STEPS + t]);

        // epilogue: thread-local cell update; h written PACKED into X[nxt]
#pragma unroll
        for (int ut = 0; ut < 4; ut++) {
            int uA = q * 32 + ut * 8 + 2 * tq;
            float hv[4];
#pragma unroll
            for (int j = 0; j < 4; j++) {
                int u = uA + (j & 1);
                float gi = acc[ut][0][j] + sb[u];
                float gf = acc[ut][1][j] + sb[128 + u];
                float gg = acc[ut][2][j] + sb[256 + u];
                float go = acc[ut][3][j] + sb[384 + u];
                float c = sigf(gf) * cst[ut][j] + sigf(gi) * tanhfast(gg);
                cst[ut][j] = c;
                hv[j] = sigf(go) * tanhfast(c);
            }
            float h0A = __bfloat162float(__float2bfloat16(hv[0]));
            float h1A = __bfloat162float(__float2bfloat16(hv[1]));
            float h0B = __bfloat162float(__float2bfloat16(hv[2]));
            float h1B = __bfloat162float(__float2bfloat16(hv[3]));
            *(uint*)&Xhi[nxt][rloc  * XS + uA] = pkbf(hv[0], hv[1]);
            *(uint*)&Xlo[nxt][rloc  * XS + uA] = pkbf(hv[0] - h0A, hv[1] - h1A);
            *(uint*)&Xhi[nxt][rlocB * XS + uA] = pkbf(hv[2], hv[3]);
            *(uint*)&Xlo[nxt][rlocB * XS + uA] = pkbf(hv[2] - h0B, hv[3] - h1B);
#pragma unroll
            for (int j = 0; j < 4; j++) {
                int u = uA + (j & 1);
                int row = (j >> 1) ? rlocB : rloc;
                float av = (j >> 1) ? avB : avA;
                float2 v = sred[row * SRS + u];
                v.x = fmaxf(v.x, hv[j]);
                v.y = fmaf(hv[j], av, v.y);
                sred[row * SRS + u] = v;
            }
            if (t == 0) {
                g_pre[(r0 + rA) * 1024 + dir * HID + uA]     = hv[0];
                g_pre[(r0 + rA) * 1024 + dir * HID + uA + 1] = hv[1];
                g_pre[(r0 + rB) * 1024 + dir * HID + uA]     = hv[2];
                g_pre[(r0 + rB) * 1024 + dir * HID + uA + 1] = hv[3];
            }
            if (t == T_STEPS - 1) {
                g_pre[(r0 + rA) * 1024 + 256 + dir * HID + uA]     = hv[0];
                g_pre[(r0 + rA) * 1024 + 256 + dir * HID + uA + 1] = hv[1];
                g_pre[(r0 + rB) * 1024 + 256 + dir * HID + uA]     = hv[2];
                g_pre[(r0 + rB) * 1024 + 256 + dir * HID + uA + 1] = hv[3];
            }
        }

        // stage e for next step into this half's X[nxt]
        if (s + 1 < T_STEPS) {
            int tn = dir ? (T_STEPS - 2 - s) : (s + 1);
            const uint4* sh = (const uint4*)(g_ehi + ((long)tn * Mrows + r0 + grp * 32) * EMBD);
            const uint4* sl = (const uint4*)(g_elo + ((long)tn * Mrows + r0 + grp * 32) * EMBD);
            int row = tidg >> 3, c8 = tidg & 7;
            *(uint4*)&Xhi[nxt][row * XS + HID + c8 * 8] = sh[tidg];
            *(uint4*)&Xlo[nxt][row * XS + HID + c8 * 8] = sl[tidg];
        }
        GBAR(grp + 1);   // half-scope barrier: the other half keeps running
        cur = nxt;
    }

    // write max / attn sections (local rows -> global)
    for (int i = tidg; i < 32 * HID; i += 256) {
        int row = i >> 7, u = i & 127;
        float2 v = sred[row * SRS + u];
        g_pre[(r0 + grp * 32 + row) * 1024 + 512 + dir * HID + u] = v.x;
        g_pre[(r0 + grp * 32 + row) * 1024 + 768 + dir * HID + u] = v.y;
    }
}

// ---------------------------------------------------------------------------
// Kernel 5: out = relu(pre(M,1024) @ enc_W(1024,128) + enc_b)
// ---------------------------------------------------------------------------
__global__ void __launch_bounds__(128)
out_kernel(const float* __restrict__ encW, const float* __restrict__ encB,
           float* __restrict__ out) {
    const int R2 = 8;
    int r0 = blockIdx.x * R2;
    int c  = threadIdx.x;
    __shared__ float2 ps[R2 / 2][64];

    float bc = encB[c];
    ull acc[R2 / 2];
#pragma unroll
    for (int p = 0; p < R2 / 2; p++) acc[p] = pack2(bc, bc);

    for (int kt = 0; kt < 1024; kt += 64) {
        __syncthreads();
#pragma unroll
        for (int i = 0; i < 4; i++) {
            int idx = c + i * 128;
            int r = idx >> 6, kk = idx & 63;
            ((float*)&ps[r >> 1][kk])[r & 1] = g_pre[(r0 + r) * 1024 + kt + kk];
        }
        __syncthreads();
#pragma unroll 4
        for (int kk = 0; kk < 64; kk++) {
            float w = encW[(kt + kk) * 128 + c];
            ull w2 = pack2(w, w);
#pragma unroll
            for (int p = 0; p < R2 / 2; p++) {
                ull pv = *(const ull*)&ps[p][kk];
                fma2(acc[p], pv, w2);
            }
        }
    }
#pragma unroll
    for (int p = 0; p < R2 / 2; p++) {
        float2 v = unpack2(acc[p]);
        out[(r0 + 2 * p)     * 128 + c] = fmaxf(v.x, 0.0f);
        out[(r0 + 2 * p + 1) * 128 + c] = fmaxf(v.y, 0.0f);
    }
}

// ---------------------------------------------------------------------------
// Launch
// ---------------------------------------------------------------------------
extern "C" void kernel_launch(void* const* d_in, const int* in_sizes, int n_in,
                              void* d_out, int out_size) {
    const float* lf    = (const float*)d_in[0];
    const float* obs   = (const float*)d_in[1];
    const float* embW  = (const float*)d_in[2];
    const float* embB  = (const float*)d_in[3];
    const float* attW  = (const float*)d_in[4];
    const float* attB  = (const float*)d_in[5];
    const float* Wih_f = (const float*)d_in[6];
    const float* Whh_f = (const float*)d_in[7];
    const float* b_f   = (const float*)d_in[8];
    const float* Wih_b = (const float*)d_in[9];
    const float* Whh_b = (const float*)d_in[10];
    const float* b_b   = (const float*)d_in[11];
    const float* h0    = (const float*)d_in[12];
    const float* c0    = (const float*)d_in[13];
    const float* encW  = (const float*)d_in[14];
    const float* encB  = (const float*)d_in[15];
    const int*   mask  = (const int*)d_in[16];

    int M    = in_sizes[16];       // 4096
    int Nobs = in_sizes[1] / 128;  // 256

    static int smem_set = 0;
    if (!smem_set) {
        cudaFuncSetAttribute(lstm_kernel,
                             cudaFuncAttributeMaxDynamicSharedMemorySize, LSTM_SMEM);
        smem_set = 1;
    }

    pack_kernel<<<(2 * 64 * KT * 32 + 255) / 256, 256>>>(Wih_f, Whh_f, Wih_b, Whh_b);
    attn_kernel<<<Nobs, 128>>>(obs, attW, attB);
    long etotal = (long)T_STEPS * M * EMBD;
    embed_kernel<<<(int)((etotal + 255) / 256), 256>>>(lf, embW, embB, M);
    lstm_kernel<<<2 * (M / MR), 512, LSTM_SMEM>>>(h0, c0, b_f, b_b, mask, M);
    out_kernel<<<M / 8, 128>>>(encW, encB, (float*)d_out);
}